// round 6
// baseline (speedup 1.0000x reference)
#include <cuda_runtime.h>
#include <cstdint>

#define L_SEQ 4096
#define BATCH 256
#define NORD  64
#define TCH   32
#define CCH   128   // L_SEQ / TCH
#define BS3   128   // batch per phase-3 CTA
#define G3    2     // BATCH / BS3

typedef unsigned long long ull;

__device__ __forceinline__ ull bcast2(float a) {
    ull r; asm("mov.b64 %0, {%1, %1};" : "=l"(r) : "f"(a)); return r;
}
__device__ __forceinline__ ull pack2(float x, float y) {
    ull r; asm("mov.b64 %0, {%1, %2};" : "=l"(r) : "f"(x), "f"(y)); return r;
}
__device__ __forceinline__ void ffma2(ull &d, ull a, ull b) {
    asm("fma.rn.f32x2 %0, %1, %2, %0;" : "+l"(d) : "l"(a), "l"(b));
}
__device__ __forceinline__ ull addx2(ull a, ull b) {
    ull r; asm("add.rn.f32x2 %0, %1, %2;" : "=l"(r) : "l"(a), "l"(b)); return r;
}
__device__ __forceinline__ float2 unpack2(ull v) {
    float2 f; asm("mov.b64 {%0, %1}, %2;" : "=f"(f.x), "=f"(f.y) : "l"(v)); return f;
}

// Scratch (static device globals: no allocations allowed)
__device__ float g_P[(size_t)CCH * NORD * NORD];   // [c][i][j]  row-major P_c   2 MB
__device__ float g_S[(size_t)CCH * BATCH * NORD];  // [c][b][i]  chunk sources   8 MB
__device__ float g_X[(size_t)CCH * BATCH * NORD];  // [c][b][i]  boundary states 8 MB

// ---------------------------------------------------------------------------
// Phase 1: per chunk c (backward over t, Pt starts as Identity):
//   w_t = (Prod_{tau>t} A_tau) B_t ;  P_c = Prod_t A_t
// then S_c[b] = sum_t inputs[t,b] * w_t.
// Pt TRANSPOSED in smem: Pt[k][i] = P[i][k].  Packed FFMA2 along i.
// Pt/As/Bs double-buffered -> ONE barrier per step.
// ---------------------------------------------------------------------------
#define P1_SMEM ((2 * NORD * NORD * 2 + TCH * NORD + 2 * NORD) * 4)

__global__ __launch_bounds__(256) void phase1_kernel(
    const float* __restrict__ A, const float* __restrict__ Bv,
    const float* __restrict__ inp)
{
    extern __shared__ float sm1[];
    float* Pt = sm1;                         // [2][64*64]
    float* As = sm1 + 2 * NORD * NORD;       // [2][64*64]
    float* W  = As  + 2 * NORD * NORD;       // [TCH][64]
    float* Bs = W   + TCH * NORD;            // [2][64]

    const int c = blockIdx.x, tid = threadIdx.x;
    const int t0 = c * TCH;
    const int ri = (tid & 15) * 4;   // i-tile
    const int cj = (tid >> 4) * 4;   // j-tile

    // init: Pt[0] = Identity; stage As[0],Bs[0] for t = TCH-1
    for (int idx = tid; idx < NORD * NORD; idx += 256)
        Pt[idx] = ((idx >> 6) == (idx & 63)) ? 1.f : 0.f;
    {
        const float4* A4 = (const float4*)(A + (size_t)(t0 + TCH - 1) * (NORD * NORD));
        float4* As4 = (float4*)As;
        #pragma unroll
        for (int q = 0; q < 4; q++) As4[tid + q * 256] = A4[tid + q * 256];
        if (tid < 16)
            ((float4*)Bs)[tid] = ((const float4*)(Bv + (size_t)(t0 + TCH - 1) * NORD))[tid];
    }
    __syncthreads();

    int cur = 0;
    #pragma unroll 1
    for (int t = TCH - 1; t >= 0; --t) {
        // prefetch next (earlier) A and B into registers
        float4 apf0, apf1, apf2, apf3, bpf;
        if (t > 0) {
            const float4* An = (const float4*)(A + (size_t)(t0 + t - 1) * (NORD * NORD));
            apf0 = An[tid]; apf1 = An[tid + 256]; apf2 = An[tid + 512]; apf3 = An[tid + 768];
            if (tid < 16) bpf = ((const float4*)(Bv + (size_t)(t0 + t - 1) * NORD))[tid];
        }

        const float* Pc = Pt + cur * (NORD * NORD);
        const float* Ac = As + cur * (NORD * NORD);
        const float* Bc = Bs + cur * NORD;

        // w_t[i] = sum_k Pt[k][i]*B_t[k]  (P BEFORE update => suffix product), 4 chains
        float w0 = 0.f, w1 = 0.f, w2 = 0.f, w3 = 0.f;
        if (tid < NORD) {
            #pragma unroll
            for (int k4 = 0; k4 < 16; k4++) {
                w0 += Pc[(4 * k4 + 0) * NORD + tid] * Bc[4 * k4 + 0];
                w1 += Pc[(4 * k4 + 1) * NORD + tid] * Bc[4 * k4 + 1];
                w2 += Pc[(4 * k4 + 2) * NORD + tid] * Bc[4 * k4 + 2];
                w3 += Pc[(4 * k4 + 3) * NORD + tid] * Bc[4 * k4 + 3];
            }
        }

        // Qt[j][i] = sum_k Pt[k][i] * A_t[k][j]  (P <- P @ A_t, kept transposed)
        ull acc2[4][2];
        #pragma unroll
        for (int jj = 0; jj < 4; jj++) { acc2[jj][0] = 0ull; acc2[jj][1] = 0ull; }

        #pragma unroll 8
        for (int k = 0; k < NORD; k++) {
            ulonglong2 p = *(const ulonglong2*)&Pc[k * NORD + ri];
            float4 a = *(const float4*)&Ac[k * NORD + cj];
            ull b0 = bcast2(a.x), b1 = bcast2(a.y), b2 = bcast2(a.z), b3 = bcast2(a.w);
            ffma2(acc2[0][0], b0, p.x); ffma2(acc2[0][1], b0, p.y);
            ffma2(acc2[1][0], b1, p.x); ffma2(acc2[1][1], b1, p.y);
            ffma2(acc2[2][0], b2, p.x); ffma2(acc2[2][1], b2, p.y);
            ffma2(acc2[3][0], b3, p.x); ffma2(acc2[3][1], b3, p.y);
        }

        if (tid < NORD) W[t * NORD + tid] = (w0 + w1) + (w2 + w3);

        const int nxt = cur ^ 1;
        if (t > 0) {
            // write new P into the OTHER buffer; stage next A/B into OTHER buffer
            float* Pn = Pt + nxt * (NORD * NORD);
            #pragma unroll
            for (int jj = 0; jj < 4; jj++)
                *(ulonglong2*)&Pn[(cj + jj) * NORD + ri] =
                    make_ulonglong2(acc2[jj][0], acc2[jj][1]);
            float4* An4 = (float4*)(As + nxt * (NORD * NORD));
            An4[tid] = apf0; An4[tid + 256] = apf1; An4[tid + 512] = apf2; An4[tid + 768] = apf3;
            if (tid < 16) ((float4*)(Bs + nxt * NORD))[tid] = bpf;
        } else {
            // final product: write g_P[c] row-major [i][j] straight from registers
            float f[4][4];
            #pragma unroll
            for (int jj = 0; jj < 4; jj++) {
                float2 v0 = unpack2(acc2[jj][0]); f[jj][0] = v0.x; f[jj][1] = v0.y;
                float2 v1 = unpack2(acc2[jj][1]); f[jj][2] = v1.x; f[jj][3] = v1.y;
            }
            float* gp = g_P + (size_t)c * (NORD * NORD);
            #pragma unroll
            for (int ii = 0; ii < 4; ii++)
                *(float4*)&gp[(ri + ii) * NORD + cj] =
                    make_float4(f[0][ii], f[1][ii], f[2][ii], f[3][ii]);
        }
        __syncthreads();
        cur = nxt;
    }

    // S_c[b][i] = sum_t W[t][i] * inputs[t0+t][b]   (thread = batch b)
    {
        float u[TCH];
        #pragma unroll
        for (int tt = 0; tt < TCH; tt++) u[tt] = inp[(size_t)(t0 + tt) * BATCH + tid];
        float* sp = g_S + ((size_t)c * BATCH + tid) * NORD;
        #pragma unroll
        for (int half = 0; half < 2; half++) {
            ull acc[16];
            #pragma unroll
            for (int m = 0; m < 16; m++) acc[m] = 0ull;
            #pragma unroll 4
            for (int tt = 0; tt < TCH; tt++) {
                ull ub = bcast2(u[tt]);
                const ull* wrow = (const ull*)&W[tt * NORD + half * 32];
                #pragma unroll
                for (int m = 0; m < 16; m++) ffma2(acc[m], ub, wrow[m]);
            }
            #pragma unroll
            for (int m2 = 0; m2 < 8; m2++)
                *(ulonglong2*)&sp[half * 32 + m2 * 4] =
                    make_ulonglong2(acc[2 * m2], acc[2 * m2 + 1]);
        }
    }
}

// ---------------------------------------------------------------------------
// Phase 2: sequential over chunks:  X_c = P_c @ X_{c-1} + S_c
// 64 CTAs x 4 batches, 256 threads: thread = (i = tid>>2, bb = tid&3).
// ---------------------------------------------------------------------------
#define P2PAD 68
__global__ __launch_bounds__(256) void phase2_kernel()
{
    __shared__ float Ps[2][NORD * P2PAD];
    __shared__ float xsm[2][4][NORD];

    const int tid = threadIdx.x;
    const int b0 = blockIdx.x * 4;
    const int i  = tid >> 2;
    const int bb = tid & 3;

    {
        const float4* gp = (const float4*)g_P;
        #pragma unroll
        for (int q = 0; q < 4; q++) {
            int f = tid + q * 256;
            int ii = f >> 4, j4 = f & 15;
            *(float4*)&Ps[0][ii * P2PAD + j4 * 4] = gp[f];
        }
        xsm[0][bb][i] = 0.f;
    }
    float s_cur = g_S[((size_t)b0 + bb) * NORD + i];
    __syncthreads();

    int cur = 0;
    #pragma unroll 1
    for (int c = 0; c < CCH; c++) {
        float4 pf0, pf1, pf2, pf3; float s_nxt = 0.f;
        if (c + 1 < CCH) {
            const float4* gp = (const float4*)(g_P + (size_t)(c + 1) * (NORD * NORD));
            pf0 = gp[tid]; pf1 = gp[tid + 256]; pf2 = gp[tid + 512]; pf3 = gp[tid + 768];
            s_nxt = g_S[((size_t)(c + 1) * BATCH + b0 + bb) * NORD + i];
        }

        ull a0 = 0ull, a1 = 0ull, a2 = 0ull, a3 = 0ull;
        const float* prow = &Ps[cur][i * P2PAD];
        const float* xrow = &xsm[cur][bb][0];
        #pragma unroll
        for (int j8 = 0; j8 < 8; j8++) {
            ulonglong2 p0 = *(const ulonglong2*)(prow + j8 * 8);
            ulonglong2 p1 = *(const ulonglong2*)(prow + j8 * 8 + 4);
            ulonglong2 x0 = *(const ulonglong2*)(xrow + j8 * 8);
            ulonglong2 x1 = *(const ulonglong2*)(xrow + j8 * 8 + 4);
            ffma2(a0, p0.x, x0.x); ffma2(a1, p0.y, x0.y);
            ffma2(a2, p1.x, x1.x); ffma2(a3, p1.y, x1.y);
        }
        float2 f0 = unpack2(a0), f1 = unpack2(a1), f2 = unpack2(a2), f3 = unpack2(a3);
        float acc = s_cur + ((f0.x + f0.y) + (f1.x + f1.y)) + ((f2.x + f2.y) + (f3.x + f3.y));

        const int nxt = cur ^ 1;
        xsm[nxt][bb][i] = acc;
        g_X[((size_t)c * BATCH + b0 + bb) * NORD + i] = acc;
        if (c + 1 < CCH) {
            #pragma unroll
            for (int q = 0; q < 4; q++) {
                float4 pv = (q == 0) ? pf0 : (q == 1) ? pf1 : (q == 2) ? pf2 : pf3;
                int f = tid + q * 256;
                int ii = f >> 4, j4 = f & 15;
                *(float4*)&Ps[nxt][ii * P2PAD + j4 * 4] = pv;
            }
        }
        s_cur = s_nxt;
        __syncthreads();
        cur = nxt;
    }
}

// ---------------------------------------------------------------------------
// Phase 3: batch-column-per-thread. Thread owns one batch b; state x[0..63]
// lives in registers packed as 32 j-pairs. A_t staged row-major in smem and
// read as warp-wide BROADCASTS (conflict-free). One barrier per step.
//   x_new[i] = B_t[i]*u + sum over j-pairs FFMA2( A[i][j-pair], x[j-pair] )
// ---------------------------------------------------------------------------
#define P3_SMEM ((2 * NORD * NORD + 2 * NORD) * 4)

__global__ __launch_bounds__(128, 2) void phase3_kernel(
    const float* __restrict__ A, const float* __restrict__ Bv,
    const float* __restrict__ inp, float* __restrict__ out)
{
    extern __shared__ float sm[];
    float* As = sm;                       // [2][64*64]  row-major A_t
    float* Bs = sm + 2 * NORD * NORD;     // [2][64]

    const int tid = threadIdx.x;
    const int c   = blockIdx.x >> 1;
    const int b   = (blockIdx.x & 1) * BS3 + tid;
    const int t0  = c * TCH;

    // stage A,B for t=0 (coalesced, conflict-free)
    {
        const float4* A4 = (const float4*)(A + (size_t)t0 * (NORD * NORD));
        float4* d = (float4*)As;
        #pragma unroll
        for (int q = 0; q < 8; q++) d[tid + q * 128] = A4[tid + q * 128];
        if (tid < 16) ((float4*)Bs)[tid] = ((const float4*)(Bv + (size_t)t0 * NORD))[tid];
    }

    // init state registers (packed j-pairs)
    ull xp[32];
    if (c == 0) {
        #pragma unroll
        for (int m = 0; m < 32; m++) xp[m] = 0ull;
    } else {
        const float4* Xp = (const float4*)(g_X + (((size_t)(c - 1)) * BATCH + b) * NORD);
        #pragma unroll
        for (int q4 = 0; q4 < 16; q4++) {
            float4 v = Xp[q4];
            xp[2 * q4]     = pack2(v.x, v.y);
            xp[2 * q4 + 1] = pack2(v.z, v.w);
        }
    }
    __syncthreads();

    int cur = 0;
    #pragma unroll 1
    for (int t = 0; t < TCH; t++) {
        // prefetch next A,B into registers (hidden under compute)
        float4 apf[8]; float4 bpf;
        if (t < TCH - 1) {
            const float4* An = (const float4*)(A + (size_t)(t0 + t + 1) * (NORD * NORD));
            #pragma unroll
            for (int q = 0; q < 8; q++) apf[q] = An[tid + q * 128];
            if (tid < 16) bpf = ((const float4*)(Bv + (size_t)(t0 + t + 1) * NORD))[tid];
        }
        const float u = inp[(size_t)(t0 + t) * BATCH + b];

        const ull* Ar = (const ull*)(As + cur * (NORD * NORD));
        const float* Bc = Bs + cur * NORD;
        float* op = out + (size_t)(t0 + t) * (BATCH * NORD) + (size_t)b * NORD;

        ull xpn[32];
        #pragma unroll
        for (int q = 0; q < 16; q++) {
            float xn[4];
            #pragma unroll
            for (int ii = 0; ii < 4; ii++) {
                const int i = q * 4 + ii;
                const ull* row = Ar + i * 32;
                ull c0 = 0ull, c1 = 0ull;
                #pragma unroll
                for (int m2 = 0; m2 < 16; m2++) {
                    ulonglong2 p = *(const ulonglong2*)(row + 2 * m2);   // broadcast
                    ffma2(c0, p.x, xp[2 * m2]);
                    ffma2(c1, p.y, xp[2 * m2 + 1]);
                }
                float2 f = unpack2(addx2(c0, c1));
                xn[ii] = fmaf(Bc[i], u, f.x + f.y);
            }
            *(float4*)(op + q * 4) = make_float4(xn[0], xn[1], xn[2], xn[3]);
            xpn[2 * q]     = pack2(xn[0], xn[1]);
            xpn[2 * q + 1] = pack2(xn[2], xn[3]);
        }
        #pragma unroll
        for (int m = 0; m < 32; m++) xp[m] = xpn[m];

        if (t < TCH - 1) {
            float4* d = (float4*)(As + (cur ^ 1) * (NORD * NORD));
            #pragma unroll
            for (int q = 0; q < 8; q++) d[tid + q * 128] = apf[q];
            if (tid < 16) ((float4*)(Bs + (cur ^ 1) * NORD))[tid] = bpf;
        }
        __syncthreads();
        cur ^= 1;
    }
}

// ---------------------------------------------------------------------------
extern "C" void kernel_launch(void* const* d_in, const int* in_sizes, int n_in,
                              void* d_out, int out_size)
{
    const float* inp = (const float*)d_in[0];   // (L, BATCH)
    const float* A   = (const float*)d_in[1];   // (L, N, N)
    const float* Bv  = (const float*)d_in[2];   // (L, N)
    float* out = (float*)d_out;                 // (L, BATCH, N)

    cudaFuncSetAttribute(phase1_kernel, cudaFuncAttributeMaxDynamicSharedMemorySize, P1_SMEM);
    cudaFuncSetAttribute(phase3_kernel, cudaFuncAttributeMaxDynamicSharedMemorySize, P3_SMEM);

    phase1_kernel<<<CCH, 256, P1_SMEM>>>(A, Bv, inp);
    phase2_kernel<<<BATCH / 4, 256>>>();
    phase3_kernel<<<CCH * G3, 128, P3_SMEM>>>(A, Bv, inp, out);
}

// round 7
// speedup vs baseline: 1.0482x; 1.0482x over previous
#include <cuda_runtime.h>
#include <cstdint>

#define L_SEQ 4096
#define BATCH 256
#define NORD  64
#define TCH   32
#define CCH   128   // L_SEQ / TCH
#define BS3   128   // batch per phase-3 CTA
#define G3    2     // BATCH / BS3

typedef unsigned long long ull;

__device__ __forceinline__ ull bcast2(float a) {
    ull r; asm("mov.b64 %0, {%1, %1};" : "=l"(r) : "f"(a)); return r;
}
__device__ __forceinline__ void ffma2(ull &d, ull a, ull b) {
    asm("fma.rn.f32x2 %0, %1, %2, %0;" : "+l"(d) : "l"(a), "l"(b));
}
__device__ __forceinline__ float2 unpack2(ull v) {
    float2 f; asm("mov.b64 {%0, %1}, %2;" : "=f"(f.x), "=f"(f.y) : "l"(v)); return f;
}

// Scratch (static device globals: no allocations allowed)
__device__ float g_P[(size_t)CCH * NORD * NORD];   // [c][i][j]  row-major P_c   2 MB
__device__ float g_S[(size_t)CCH * BATCH * NORD];  // [c][b][i]  chunk sources   8 MB
__device__ float g_X[(size_t)CCH * BATCH * NORD];  // [c][b][i]  boundary states 8 MB

// ---------------------------------------------------------------------------
// Phase 1: per chunk c (backward over t, Pt starts as Identity):
//   w_t = (Prod_{tau>t} A_tau) B_t ;  P_c = Prod_t A_t
// then S_c[b] = sum_t inputs[t,b] * w_t.
// Pt TRANSPOSED in smem; double-buffered; 512 threads (4i x 2j tiles) for
// latency hiding (4 warps/SMSP). ONE barrier per step.
// ---------------------------------------------------------------------------
#define P1_SMEM ((2 * NORD * NORD * 2 + TCH * NORD + 2 * NORD) * 4)

__global__ __launch_bounds__(512) void phase1_kernel(
    const float* __restrict__ A, const float* __restrict__ Bv,
    const float* __restrict__ inp)
{
    extern __shared__ float sm1[];
    float* Pt = sm1;                         // [2][64*64]
    float* As = sm1 + 2 * NORD * NORD;       // [2][64*64]
    float* W  = As  + 2 * NORD * NORD;       // [TCH][64]
    float* Bs = W   + TCH * NORD;            // [2][64]

    const int c = blockIdx.x, tid = threadIdx.x;
    const int t0 = c * TCH;
    const int ri = (tid & 15) * 4;   // i-tile (4, as 2 packed pairs)
    const int cj = (tid >> 4) * 2;   // j-tile (2)

    // init: Pt[0] = Identity; stage As[0],Bs[0] for t = TCH-1
    for (int idx = tid; idx < NORD * NORD; idx += 512)
        Pt[idx] = ((idx >> 6) == (idx & 63)) ? 1.f : 0.f;
    {
        const float4* A4 = (const float4*)(A + (size_t)(t0 + TCH - 1) * (NORD * NORD));
        float4* As4 = (float4*)As;
        As4[tid] = A4[tid]; As4[tid + 512] = A4[tid + 512];
        if (tid < 16)
            ((float4*)Bs)[tid] = ((const float4*)(Bv + (size_t)(t0 + TCH - 1) * NORD))[tid];
    }
    __syncthreads();

    int cur = 0;
    #pragma unroll 1
    for (int t = TCH - 1; t >= 0; --t) {
        // prefetch next (earlier) A and B into registers
        float4 apf0, apf1; float4 bpf;
        if (t > 0) {
            const float4* An = (const float4*)(A + (size_t)(t0 + t - 1) * (NORD * NORD));
            apf0 = An[tid]; apf1 = An[tid + 512];
            if (tid < 16) bpf = ((const float4*)(Bv + (size_t)(t0 + t - 1) * NORD))[tid];
        }

        const float* Pc = Pt + cur * (NORD * NORD);
        const float* Ac = As + cur * (NORD * NORD);
        const float* Bc = Bs + cur * NORD;

        // w_t[i] = sum_k Pt[k][i]*B_t[k]  (P BEFORE update => suffix), 4 chains
        float w0 = 0.f, w1 = 0.f, w2 = 0.f, w3 = 0.f;
        if (tid < NORD) {
            #pragma unroll
            for (int k4 = 0; k4 < 16; k4++) {
                w0 += Pc[(4 * k4 + 0) * NORD + tid] * Bc[4 * k4 + 0];
                w1 += Pc[(4 * k4 + 1) * NORD + tid] * Bc[4 * k4 + 1];
                w2 += Pc[(4 * k4 + 2) * NORD + tid] * Bc[4 * k4 + 2];
                w3 += Pc[(4 * k4 + 3) * NORD + tid] * Bc[4 * k4 + 3];
            }
        }

        // Qt[j][i] = sum_k Pt[k][i] * A_t[k][j]  (P <- P @ A_t, kept transposed)
        ull acc2[2][2];
        acc2[0][0] = 0ull; acc2[0][1] = 0ull; acc2[1][0] = 0ull; acc2[1][1] = 0ull;

        #pragma unroll 8
        for (int k = 0; k < NORD; k++) {
            ulonglong2 p = *(const ulonglong2*)&Pc[k * NORD + ri];
            float2 a = *(const float2*)&Ac[k * NORD + cj];
            ull b0 = bcast2(a.x), b1 = bcast2(a.y);
            ffma2(acc2[0][0], b0, p.x); ffma2(acc2[0][1], b0, p.y);
            ffma2(acc2[1][0], b1, p.x); ffma2(acc2[1][1], b1, p.y);
        }

        if (tid < NORD) W[t * NORD + tid] = (w0 + w1) + (w2 + w3);

        const int nxt = cur ^ 1;
        if (t > 0) {
            float* Pn = Pt + nxt * (NORD * NORD);
            #pragma unroll
            for (int jj = 0; jj < 2; jj++)
                *(ulonglong2*)&Pn[(cj + jj) * NORD + ri] =
                    make_ulonglong2(acc2[jj][0], acc2[jj][1]);
            float4* An4 = (float4*)(As + nxt * (NORD * NORD));
            An4[tid] = apf0; An4[tid + 512] = apf1;
            if (tid < 16) ((float4*)(Bs + nxt * NORD))[tid] = bpf;
        } else {
            // final product: write g_P[c] row-major [i][j] straight from regs
            float f[2][4];
            #pragma unroll
            for (int jj = 0; jj < 2; jj++) {
                float2 v0 = unpack2(acc2[jj][0]); f[jj][0] = v0.x; f[jj][1] = v0.y;
                float2 v1 = unpack2(acc2[jj][1]); f[jj][2] = v1.x; f[jj][3] = v1.y;
            }
            float* gp = g_P + (size_t)c * (NORD * NORD);
            #pragma unroll
            for (int ii = 0; ii < 4; ii++)
                *(float2*)&gp[(ri + ii) * NORD + cj] = make_float2(f[0][ii], f[1][ii]);
        }
        __syncthreads();
        cur = nxt;
    }

    // S_c[b][i] = sum_t W[t][i] * inputs[t0+t][b]
    // 512 threads: b = tid&255, half = tid>>8 (32 i's each)
    {
        const int b = tid & 255, half = tid >> 8;
        float u[TCH];
        #pragma unroll
        for (int tt = 0; tt < TCH; tt++) u[tt] = inp[(size_t)(t0 + tt) * BATCH + b];
        float* sp = g_S + ((size_t)c * BATCH + b) * NORD;
        ull acc[16];
        #pragma unroll
        for (int m = 0; m < 16; m++) acc[m] = 0ull;
        #pragma unroll 4
        for (int tt = 0; tt < TCH; tt++) {
            ull ub = bcast2(u[tt]);
            const ull* wrow = (const ull*)&W[tt * NORD + half * 32];
            #pragma unroll
            for (int m = 0; m < 16; m++) ffma2(acc[m], ub, wrow[m]);
        }
        #pragma unroll
        for (int m2 = 0; m2 < 8; m2++)
            *(ulonglong2*)&sp[half * 32 + m2 * 4] =
                make_ulonglong2(acc[2 * m2], acc[2 * m2 + 1]);
    }
}

// ---------------------------------------------------------------------------
// Phase 2: sequential over chunks:  X_c = P_c @ X_{c-1} + S_c
// 64 CTAs x 4 batches, 256 threads: thread = (i = tid>>2, bb = tid&3).
// ---------------------------------------------------------------------------
#define P2PAD 68
__global__ __launch_bounds__(256) void phase2_kernel()
{
    __shared__ float Ps[2][NORD * P2PAD];
    __shared__ float xsm[2][4][NORD];

    const int tid = threadIdx.x;
    const int b0 = blockIdx.x * 4;
    const int i  = tid >> 2;
    const int bb = tid & 3;

    {
        const float4* gp = (const float4*)g_P;
        #pragma unroll
        for (int q = 0; q < 4; q++) {
            int f = tid + q * 256;
            int ii = f >> 4, j4 = f & 15;
            *(float4*)&Ps[0][ii * P2PAD + j4 * 4] = gp[f];
        }
        xsm[0][bb][i] = 0.f;
    }
    float s_cur = g_S[((size_t)b0 + bb) * NORD + i];
    __syncthreads();

    int cur = 0;
    #pragma unroll 1
    for (int c = 0; c < CCH; c++) {
        float4 pf0, pf1, pf2, pf3; float s_nxt = 0.f;
        if (c + 1 < CCH) {
            const float4* gp = (const float4*)(g_P + (size_t)(c + 1) * (NORD * NORD));
            pf0 = gp[tid]; pf1 = gp[tid + 256]; pf2 = gp[tid + 512]; pf3 = gp[tid + 768];
            s_nxt = g_S[((size_t)(c + 1) * BATCH + b0 + bb) * NORD + i];
        }

        ull a0 = 0ull, a1 = 0ull, a2 = 0ull, a3 = 0ull;
        const float* prow = &Ps[cur][i * P2PAD];
        const float* xrow = &xsm[cur][bb][0];
        #pragma unroll
        for (int j8 = 0; j8 < 8; j8++) {
            ulonglong2 p0 = *(const ulonglong2*)(prow + j8 * 8);
            ulonglong2 p1 = *(const ulonglong2*)(prow + j8 * 8 + 4);
            ulonglong2 x0 = *(const ulonglong2*)(xrow + j8 * 8);
            ulonglong2 x1 = *(const ulonglong2*)(xrow + j8 * 8 + 4);
            ffma2(a0, p0.x, x0.x); ffma2(a1, p0.y, x0.y);
            ffma2(a2, p1.x, x1.x); ffma2(a3, p1.y, x1.y);
        }
        float2 f0 = unpack2(a0), f1 = unpack2(a1), f2 = unpack2(a2), f3 = unpack2(a3);
        float acc = s_cur + ((f0.x + f0.y) + (f1.x + f1.y)) + ((f2.x + f2.y) + (f3.x + f3.y));

        const int nxt = cur ^ 1;
        xsm[nxt][bb][i] = acc;
        g_X[((size_t)c * BATCH + b0 + bb) * NORD + i] = acc;
        if (c + 1 < CCH) {
            #pragma unroll
            for (int q = 0; q < 4; q++) {
                float4 pv = (q == 0) ? pf0 : (q == 1) ? pf1 : (q == 2) ? pf2 : pf3;
                int f = tid + q * 256;
                int ii = f >> 4, j4 = f & 15;
                *(float4*)&Ps[nxt][ii * P2PAD + j4 * 4] = pv;
            }
        }
        s_cur = s_nxt;
        __syncthreads();
        cur = nxt;
    }
}

// ---------------------------------------------------------------------------
// Phase 3: per (chunk, batch-half): scan TCH steps, writing all outputs.
// Per-step: Xnew(64x128) = A_t @ X + B_t (x) u_t.  128 threads.
// SPLIT batch tile: thread (q=tid&15, riq=tid>>4) owns batches {4q..4q+3} and
// {64+4q..64+4q+3}, rows 8*riq..+7.  All xs LDS/STS are lane-contiguous 16B
// -> conflict-free (this was the round-4 4-way-conflict bottleneck).
// State in smem (no register spill), acc in 64 regs, FFMA2 packed along batch.
// ---------------------------------------------------------------------------
#define P3_APAD 68
#define P3_SMEM ((NORD * P3_APAD + NORD * BS3 + NORD) * 4)

__device__ __forceinline__ void p3_stage_A(float* As, const float4* apf, int tid) {
    #pragma unroll
    for (int q = 0; q < 8; q++) {
        int f = tid + q * 128;              // float4 index: i = f>>4, j = 4*(f&15)
        int i = f >> 4, j = (f & 15) * 4;
        float4 v = apf[q];
        As[(j + 0) * P3_APAD + i] = v.x;
        As[(j + 1) * P3_APAD + i] = v.y;
        As[(j + 2) * P3_APAD + i] = v.z;
        As[(j + 3) * P3_APAD + i] = v.w;
    }
}

__global__ __launch_bounds__(128, 2) void phase3_kernel(
    const float* __restrict__ A, const float* __restrict__ Bv,
    const float* __restrict__ inp, float* __restrict__ out)
{
    extern __shared__ float sm[];
    float* As = sm;                       // [64][68]  As[k][i] = A[i][k]
    float* xs = sm + NORD * P3_APAD;      // [64][128] xs[j][b]
    float* Bs = xs + NORD * BS3;          // [64]

    const int c  = blockIdx.x >> 1;
    const int b0 = (blockIdx.x & 1) * BS3;
    const int tid = threadIdx.x;
    const int bq = (tid & 15) * 4;        // batch sub-tile base (lo half)
    const int riq = (tid >> 4);
    const int ri = riq * 8;
    const int t0 = c * TCH;

    // stage A,B for t=0
    {
        const float4* A4 = (const float4*)(A + (size_t)t0 * (NORD * NORD));
        float4 apf[8];
        #pragma unroll
        for (int q = 0; q < 8; q++) apf[q] = A4[tid + q * 128];
        p3_stage_A(As, apf, tid);
        if (tid < 16) ((float4*)Bs)[tid] = ((const float4*)(Bv + (size_t)t0 * NORD))[tid];
    }

    // load initial state (transposed into [j][b]); thread = batch column tid
    if (c == 0) {
        for (int idx = tid; idx < NORD * BS3; idx += 128) xs[idx] = 0.f;
    } else {
        const float4* Xp = (const float4*)(g_X + (((size_t)(c - 1)) * BATCH + b0 + tid) * NORD);
        #pragma unroll
        for (int j4 = 0; j4 < 16; j4++) {
            float4 v = Xp[j4];
            xs[(j4 * 4 + 0) * BS3 + tid] = v.x;
            xs[(j4 * 4 + 1) * BS3 + tid] = v.y;
            xs[(j4 * 4 + 2) * BS3 + tid] = v.z;
            xs[(j4 * 4 + 3) * BS3 + tid] = v.w;
        }
    }
    __syncthreads();

    #pragma unroll 1
    for (int t = 0; t < TCH; t++) {
        // prefetch next A,B
        float4 apf[8]; float4 bpf;
        if (t < TCH - 1) {
            const float4* An = (const float4*)(A + (size_t)(t0 + t + 1) * (NORD * NORD));
            #pragma unroll
            for (int q = 0; q < 8; q++) apf[q] = An[tid + q * 128];
            if (tid < 16) bpf = ((const float4*)(Bv + (size_t)(t0 + t + 1) * NORD))[tid];
        }

        ull acc2[8][4];
        #pragma unroll
        for (int r = 0; r < 8; r++)
            #pragma unroll
            for (int q = 0; q < 4; q++) acc2[r][q] = 0ull;

        const float4* As4 = (const float4*)As;
        #pragma unroll 8
        for (int k = 0; k < NORD; k++) {
            float4 a0 = As4[k * (P3_APAD / 4) + riq * 2];
            float4 a1 = As4[k * (P3_APAD / 4) + riq * 2 + 1];
            // conflict-free: lane-contiguous 16B in each batch half
            ulonglong2 x0 = *(const ulonglong2*)&xs[k * BS3 + bq];
            ulonglong2 x1 = *(const ulonglong2*)&xs[k * BS3 + 64 + bq];
            float av[8] = {a0.x, a0.y, a0.z, a0.w, a1.x, a1.y, a1.z, a1.w};
            #pragma unroll
            for (int r = 0; r < 8; r++) {
                ull ab = bcast2(av[r]);
                ffma2(acc2[r][0], ab, x0.x); ffma2(acc2[r][1], ab, x0.y);
                ffma2(acc2[r][2], ab, x1.x); ffma2(acc2[r][3], ab, x1.y);
            }
        }

        // + B_t[i] * u_t[b]
        {
            const float* up = inp + (size_t)(t0 + t) * BATCH + b0;
            ulonglong2 u0 = *(const ulonglong2*)(up + bq);
            ulonglong2 u1 = *(const ulonglong2*)(up + 64 + bq);
            #pragma unroll
            for (int r = 0; r < 8; r++) {
                ull ab = bcast2(Bs[ri + r]);
                ffma2(acc2[r][0], ab, u0.x); ffma2(acc2[r][1], ab, u0.y);
                ffma2(acc2[r][2], ab, u1.x); ffma2(acc2[r][3], ab, u1.y);
            }
        }
        __syncthreads();   // done reading xs/As/Bs

        // update state (conflict-free lane-contiguous stores)
        #pragma unroll
        for (int r = 0; r < 8; r++) {
            *(ulonglong2*)&xs[(ri + r) * BS3 + bq]      = make_ulonglong2(acc2[r][0], acc2[r][1]);
            *(ulonglong2*)&xs[(ri + r) * BS3 + 64 + bq] = make_ulonglong2(acc2[r][2], acc2[r][3]);
        }
        // write output x_t: q2 -> batch cols {bq+2*q2 lo/hi} in each half
        float* ob = out + (size_t)(t0 + t) * (BATCH * NORD) + (size_t)b0 * NORD + ri;
        #pragma unroll
        for (int q2 = 0; q2 < 4; q2++) {
            const int bc = (q2 < 2) ? (bq + 2 * q2) : (64 + bq + 2 * (q2 - 2));
            float lo[8], hi[8];
            #pragma unroll
            for (int r = 0; r < 8; r++) {
                float2 v = unpack2(acc2[r][q2]);
                lo[r] = v.x; hi[r] = v.y;
            }
            float* op = ob + (size_t)bc * NORD;
            *(float4*)op              = make_float4(lo[0], lo[1], lo[2], lo[3]);
            *(float4*)(op + 4)        = make_float4(lo[4], lo[5], lo[6], lo[7]);
            *(float4*)(op + NORD)     = make_float4(hi[0], hi[1], hi[2], hi[3]);
            *(float4*)(op + NORD + 4) = make_float4(hi[4], hi[5], hi[6], hi[7]);
        }

        if (t < TCH - 1) {
            p3_stage_A(As, apf, tid);
            if (tid < 16) ((float4*)Bs)[tid] = bpf;
        }
        __syncthreads();
    }
}

// ---------------------------------------------------------------------------
extern "C" void kernel_launch(void* const* d_in, const int* in_sizes, int n_in,
                              void* d_out, int out_size)
{
    const float* inp = (const float*)d_in[0];   // (L, BATCH)
    const float* A   = (const float*)d_in[1];   // (L, N, N)
    const float* Bv  = (const float*)d_in[2];   // (L, N)
    float* out = (float*)d_out;                 // (L, BATCH, N)

    cudaFuncSetAttribute(phase1_kernel, cudaFuncAttributeMaxDynamicSharedMemorySize, P1_SMEM);
    cudaFuncSetAttribute(phase3_kernel, cudaFuncAttributeMaxDynamicSharedMemorySize, P3_SMEM);

    phase1_kernel<<<CCH, 512, P1_SMEM>>>(A, Bv, inp);
    phase2_kernel<<<BATCH / 4, 256>>>();
    phase3_kernel<<<CCH * G3, 128, P3_SMEM>>>(A, Bv, inp, out);
}

// round 8
// speedup vs baseline: 1.0963x; 1.0459x over previous
#include <cuda_runtime.h>
#include <cstdint>

#define L_SEQ 4096
#define BATCH 256
#define NORD  64
#define TCH   32
#define CCH   128   // L_SEQ / TCH

typedef unsigned long long ull;

__device__ __forceinline__ ull bcast2(float a) {
    ull r; asm("mov.b64 %0, {%1, %1};" : "=l"(r) : "f"(a)); return r;
}
__device__ __forceinline__ void ffma2(ull &d, ull a, ull b) {
    asm("fma.rn.f32x2 %0, %1, %2, %0;" : "+l"(d) : "l"(a), "l"(b));
}
__device__ __forceinline__ float2 unpack2(ull v) {
    float2 f; asm("mov.b64 {%0, %1}, %2;" : "=f"(f.x), "=f"(f.y) : "l"(v)); return f;
}

// Scratch (static device globals: no allocations allowed)
__device__ float g_P[(size_t)CCH * NORD * NORD];   // [c][i][j]  row-major P_c   2 MB
__device__ float g_S[(size_t)CCH * BATCH * NORD];  // [c][b][i]  chunk sources   8 MB
__device__ float g_X[(size_t)CCH * BATCH * NORD];  // [c][b][i]  boundary states 8 MB

// ---------------------------------------------------------------------------
// Phase 1 (round-4 version, 256 threads — measured 93-94us):
// per chunk c (backward over t, Pt starts as Identity):
//   w_t = (Prod_{tau>t} A_tau) B_t ;  P_c = Prod_t A_t
// then S_c[b] = sum_t inputs[t,b] * w_t.
// ---------------------------------------------------------------------------
__global__ __launch_bounds__(256) void phase1_kernel(
    const float* __restrict__ A, const float* __restrict__ Bv,
    const float* __restrict__ inp)
{
    __shared__ float Pt[NORD * NORD];
    __shared__ float As[NORD * NORD];
    __shared__ float Bs[NORD];
    __shared__ float W[TCH][NORD];

    const int c = blockIdx.x, tid = threadIdx.x;
    const int t0 = c * TCH;
    const int ri = (tid & 15) * 4;   // i-tile
    const int cj = (tid >> 4) * 4;   // j-tile

    // init: Pt = Identity; stage A,B for t = TCH-1
    for (int idx = tid; idx < NORD * NORD; idx += 256)
        Pt[idx] = ((idx >> 6) == (idx & 63)) ? 1.f : 0.f;
    {
        const float4* A4 = (const float4*)(A + (size_t)(t0 + TCH - 1) * (NORD * NORD));
        float4* As4 = (float4*)As;
        #pragma unroll
        for (int q = 0; q < 4; q++) As4[tid + q * 256] = A4[tid + q * 256];
        if (tid < 16)
            ((float4*)Bs)[tid] = ((const float4*)(Bv + (size_t)(t0 + TCH - 1) * NORD))[tid];
    }
    __syncthreads();

    #pragma unroll 1
    for (int t = TCH - 1; t >= 0; --t) {
        // prefetch next (earlier) A and B into registers
        float4 apf0, apf1, apf2, apf3, bpf;
        if (t > 0) {
            const float4* An = (const float4*)(A + (size_t)(t0 + t - 1) * (NORD * NORD));
            apf0 = An[tid]; apf1 = An[tid + 256]; apf2 = An[tid + 512]; apf3 = An[tid + 768];
            if (tid < 16) bpf = ((const float4*)(Bv + (size_t)(t0 + t - 1) * NORD))[tid];
        }

        // w_t[i] = sum_k Pt[k][i]*B_t[k]  (P BEFORE update => suffix), 4 chains
        float w0 = 0.f, w1 = 0.f, w2 = 0.f, w3 = 0.f;
        if (tid < NORD) {
            #pragma unroll
            for (int k4 = 0; k4 < 16; k4++) {
                w0 += Pt[(4 * k4 + 0) * NORD + tid] * Bs[4 * k4 + 0];
                w1 += Pt[(4 * k4 + 1) * NORD + tid] * Bs[4 * k4 + 1];
                w2 += Pt[(4 * k4 + 2) * NORD + tid] * Bs[4 * k4 + 2];
                w3 += Pt[(4 * k4 + 3) * NORD + tid] * Bs[4 * k4 + 3];
            }
        }

        // Qt[j][i] = sum_k Pt[k][i] * A_t[k][j]  (P <- P @ A_t, kept transposed)
        ull acc2[4][2];
        #pragma unroll
        for (int jj = 0; jj < 4; jj++) { acc2[jj][0] = 0ull; acc2[jj][1] = 0ull; }

        #pragma unroll 8
        for (int k = 0; k < NORD; k++) {
            ulonglong2 p = *(const ulonglong2*)&Pt[k * NORD + ri];
            float4 a = *(const float4*)&As[k * NORD + cj];
            ull b0 = bcast2(a.x), b1 = bcast2(a.y), b2 = bcast2(a.z), b3 = bcast2(a.w);
            ffma2(acc2[0][0], b0, p.x); ffma2(acc2[0][1], b0, p.y);
            ffma2(acc2[1][0], b1, p.x); ffma2(acc2[1][1], b1, p.y);
            ffma2(acc2[2][0], b2, p.x); ffma2(acc2[2][1], b2, p.y);
            ffma2(acc2[3][0], b3, p.x); ffma2(acc2[3][1], b3, p.y);
        }
        __syncthreads();           // done reading Pt, As, Bs

        if (tid < NORD) W[t][tid] = (w0 + w1) + (w2 + w3);
        if (t > 0) {
            #pragma unroll
            for (int jj = 0; jj < 4; jj++)
                *(ulonglong2*)&Pt[(cj + jj) * NORD + ri] =
                    make_ulonglong2(acc2[jj][0], acc2[jj][1]);
            float4* As4 = (float4*)As;
            As4[tid] = apf0; As4[tid + 256] = apf1; As4[tid + 512] = apf2; As4[tid + 768] = apf3;
            if (tid < 16) ((float4*)Bs)[tid] = bpf;
        } else {
            // final product: write g_P[c] row-major [i][j] straight from registers
            float f[4][4];
            #pragma unroll
            for (int jj = 0; jj < 4; jj++) {
                float2 v0 = unpack2(acc2[jj][0]); f[jj][0] = v0.x; f[jj][1] = v0.y;
                float2 v1 = unpack2(acc2[jj][1]); f[jj][2] = v1.x; f[jj][3] = v1.y;
            }
            float* gp = g_P + (size_t)c * (NORD * NORD);
            #pragma unroll
            for (int ii = 0; ii < 4; ii++)
                *(float4*)&gp[(ri + ii) * NORD + cj] =
                    make_float4(f[0][ii], f[1][ii], f[2][ii], f[3][ii]);
        }
        __syncthreads();
    }

    // S_c[b][i] = sum_t W[t][i] * inputs[t0+t][b]   (thread = batch b)
    {
        float u[TCH];
        #pragma unroll
        for (int tt = 0; tt < TCH; tt++) u[tt] = inp[(size_t)(t0 + tt) * BATCH + tid];
        float* sp = g_S + ((size_t)c * BATCH + tid) * NORD;
        #pragma unroll
        for (int half = 0; half < 2; half++) {
            ull acc[16];
            #pragma unroll
            for (int m = 0; m < 16; m++) acc[m] = 0ull;
            #pragma unroll 4
            for (int tt = 0; tt < TCH; tt++) {
                ull ub = bcast2(u[tt]);
                const ull* wrow = (const ull*)&W[tt][half * 32];
                #pragma unroll
                for (int m = 0; m < 16; m++) ffma2(acc[m], ub, wrow[m]);
            }
            #pragma unroll
            for (int m2 = 0; m2 < 8; m2++)
                *(ulonglong2*)&sp[half * 32 + m2 * 4] =
                    make_ulonglong2(acc[2 * m2], acc[2 * m2 + 1]);
        }
    }
}

// ---------------------------------------------------------------------------
// Phase 2: sequential over chunks:  X_c = P_c @ X_{c-1} + S_c
// 64 CTAs x 4 batches, 256 threads: thread = (i = tid>>2, bb = tid&3).
// ---------------------------------------------------------------------------
#define P2PAD 68
__global__ __launch_bounds__(256) void phase2_kernel()
{
    __shared__ float Ps[2][NORD * P2PAD];
    __shared__ float xsm[2][4][NORD];

    const int tid = threadIdx.x;
    const int b0 = blockIdx.x * 4;
    const int i  = tid >> 2;
    const int bb = tid & 3;

    {
        const float4* gp = (const float4*)g_P;
        #pragma unroll
        for (int q = 0; q < 4; q++) {
            int f = tid + q * 256;
            int ii = f >> 4, j4 = f & 15;
            *(float4*)&Ps[0][ii * P2PAD + j4 * 4] = gp[f];
        }
        xsm[0][bb][i] = 0.f;
    }
    float s_cur = g_S[((size_t)b0 + bb) * NORD + i];
    __syncthreads();

    int cur = 0;
    #pragma unroll 1
    for (int c = 0; c < CCH; c++) {
        float4 pf0, pf1, pf2, pf3; float s_nxt = 0.f;
        if (c + 1 < CCH) {
            const float4* gp = (const float4*)(g_P + (size_t)(c + 1) * (NORD * NORD));
            pf0 = gp[tid]; pf1 = gp[tid + 256]; pf2 = gp[tid + 512]; pf3 = gp[tid + 768];
            s_nxt = g_S[((size_t)(c + 1) * BATCH + b0 + bb) * NORD + i];
        }

        ull a0 = 0ull, a1 = 0ull, a2 = 0ull, a3 = 0ull;
        const float* prow = &Ps[cur][i * P2PAD];
        const float* xrow = &xsm[cur][bb][0];
        #pragma unroll
        for (int j8 = 0; j8 < 8; j8++) {
            ulonglong2 p0 = *(const ulonglong2*)(prow + j8 * 8);
            ulonglong2 p1 = *(const ulonglong2*)(prow + j8 * 8 + 4);
            ulonglong2 x0 = *(const ulonglong2*)(xrow + j8 * 8);
            ulonglong2 x1 = *(const ulonglong2*)(xrow + j8 * 8 + 4);
            ffma2(a0, p0.x, x0.x); ffma2(a1, p0.y, x0.y);
            ffma2(a2, p1.x, x1.x); ffma2(a3, p1.y, x1.y);
        }
        float2 f0 = unpack2(a0), f1 = unpack2(a1), f2 = unpack2(a2), f3 = unpack2(a3);
        float acc = s_cur + ((f0.x + f0.y) + (f1.x + f1.y)) + ((f2.x + f2.y) + (f3.x + f3.y));

        const int nxt = cur ^ 1;
        xsm[nxt][bb][i] = acc;
        g_X[((size_t)c * BATCH + b0 + bb) * NORD + i] = acc;
        if (c + 1 < CCH) {
            #pragma unroll
            for (int q = 0; q < 4; q++) {
                float4 pv = (q == 0) ? pf0 : (q == 1) ? pf1 : (q == 2) ? pf2 : pf3;
                int f = tid + q * 256;
                int ii = f >> 4, j4 = f & 15;
                *(float4*)&Ps[nxt][ii * P2PAD + j4 * 4] = pv;
            }
        }
        s_cur = s_nxt;
        __syncthreads();
        cur = nxt;
    }
}

// ---------------------------------------------------------------------------
// Phase 3 (NEW): one CTA per chunk (grid=128, single wave), 256 threads,
// full 256-batch tile.  A_t is LOWER TRIANGULAR -> skip upper-triangle work
// with warp-uniform bounds.
// Thread (riq = tid>>5, bq = 8*(tid&31)) owns rows {riq+8m, m=0..7}
// (interleaved for balance; riq is warp-uniform) x batches bq..bq+7.
// Row r needs k <= r.  k-blocks aligned to riq:
//   block0:      k in [0, riq],              rows m = 0..7
//   KBLOCK(MB):  k in [riq+8(MB-1)+1, riq+8MB], rows m = MB..7
// State xs[j][b] in smem (stride 256, all accesses conflict-free-throughput);
// outputs routed through xs -> coalesced STG.  2 barriers/step.
// ---------------------------------------------------------------------------
#define P3_APAD 68
#define P3_SMEM ((2 * NORD * P3_APAD + NORD * BATCH + 2 * NORD) * 4)

__device__ __forceinline__ void p3_stage_A(float* As, const float4* apf, int tid) {
    #pragma unroll
    for (int q = 0; q < 4; q++) {
        int f = tid + q * 256;              // float4 index: i = f>>4, j = 4*(f&15)
        int i = f >> 4, j = (f & 15) * 4;
        float4 v = apf[q];
        As[(j + 0) * P3_APAD + i] = v.x;
        As[(j + 1) * P3_APAD + i] = v.y;
        As[(j + 2) * P3_APAD + i] = v.z;
        As[(j + 3) * P3_APAD + i] = v.w;
    }
}

__global__ __launch_bounds__(256, 1) void phase3_kernel(
    const float* __restrict__ A, const float* __restrict__ Bv,
    const float* __restrict__ inp, float* __restrict__ out)
{
    extern __shared__ float sm[];
    float* As = sm;                           // [2][64][68]  As[k][i] = A[i][k]
    float* xs = sm + 2 * NORD * P3_APAD;      // [64][256]    xs[j][b]
    float* Bs = xs + NORD * BATCH;            // [2][64]

    const int tid = threadIdx.x;
    const int c   = blockIdx.x;
    const int t0  = c * TCH;
    const int riq = tid >> 5;                 // warp-uniform row offset 0..7
    const int bq  = (tid & 31) * 8;           // batch sub-tile

    // stage A,B for t=0
    {
        const float4* A4 = (const float4*)(A + (size_t)t0 * (NORD * NORD));
        float4 apf[4];
        #pragma unroll
        for (int q = 0; q < 4; q++) apf[q] = A4[tid + q * 256];
        p3_stage_A(As, apf, tid);
        if (tid < 16) ((float4*)Bs)[tid] = ((const float4*)(Bv + (size_t)t0 * NORD))[tid];
    }

    // load initial state into xs[j][b] (thread = batch column tid)
    if (c == 0) {
        for (int idx = tid; idx < NORD * BATCH; idx += 256) xs[idx] = 0.f;
    } else {
        const float4* Xp = (const float4*)(g_X + (((size_t)(c - 1)) * BATCH + tid) * NORD);
        #pragma unroll
        for (int j4 = 0; j4 < 16; j4++) {
            float4 v = Xp[j4];
            xs[(j4 * 4 + 0) * BATCH + tid] = v.x;
            xs[(j4 * 4 + 1) * BATCH + tid] = v.y;
            xs[(j4 * 4 + 2) * BATCH + tid] = v.z;
            xs[(j4 * 4 + 3) * BATCH + tid] = v.w;
        }
    }
    __syncthreads();

    int cur = 0;
    #pragma unroll 1
    for (int t = 0; t < TCH; t++) {
        // prefetch next A,B into registers
        float4 apf[4]; float4 bpf;
        if (t < TCH - 1) {
            const float4* An = (const float4*)(A + (size_t)(t0 + t + 1) * (NORD * NORD));
            #pragma unroll
            for (int q = 0; q < 4; q++) apf[q] = An[tid + q * 256];
            if (tid < 16) bpf = ((const float4*)(Bv + (size_t)(t0 + t + 1) * NORD))[tid];
        }

        const float* Ac = As + cur * (NORD * P3_APAD);
        const float* Bc = Bs + cur * NORD;

        // init acc[m] = B[row] * u[b]
        ull acc[8][4];
        {
            const float* up = inp + (size_t)(t0 + t) * BATCH + bq;
            ulonglong2 u0 = *(const ulonglong2*)up;
            ulonglong2 u1 = *(const ulonglong2*)(up + 4);
            #pragma unroll
            for (int m = 0; m < 8; m++) {
                ull ab = bcast2(Bc[riq + 8 * m]);
                acc[m][0] = 0ull; acc[m][1] = 0ull; acc[m][2] = 0ull; acc[m][3] = 0ull;
                ffma2(acc[m][0], ab, u0.x); ffma2(acc[m][1], ab, u0.y);
                ffma2(acc[m][2], ab, u1.x); ffma2(acc[m][3], ab, u1.y);
            }
        }

        // triangular MACs: row = riq+8m needs k <= row
        #define P3_ACCK(K, MSTART)                                              \
        {                                                                       \
            ulonglong2 X0 = *(const ulonglong2*)&xs[(K) * BATCH + bq];          \
            ulonglong2 X1 = *(const ulonglong2*)&xs[(K) * BATCH + bq + 4];      \
            _Pragma("unroll")                                                   \
            for (int m = (MSTART); m < 8; m++) {                                \
                ull ab = bcast2(Ac[(K) * P3_APAD + riq + 8 * m]);               \
                ffma2(acc[m][0], ab, X0.x); ffma2(acc[m][1], ab, X0.y);         \
                ffma2(acc[m][2], ab, X1.x); ffma2(acc[m][3], ab, X1.y);         \
            }                                                                   \
        }

        // block 0: k = 0..riq (runtime trip <= 8, warp-uniform), all rows
        #pragma unroll 1
        for (int k = 0; k <= riq; k++) P3_ACCK(k, 0);

        // KBLOCK(MB): 8 k's, rows m >= MB
        #define P3_KBLOCK(MB)                                                   \
        {                                                                       \
            const int kbase = riq + 8 * ((MB) - 1) + 1;                         \
            _Pragma("unroll")                                                   \
            for (int kk = 0; kk < 8; kk++) P3_ACCK(kbase + kk, MB);             \
        }
        P3_KBLOCK(1) P3_KBLOCK(2) P3_KBLOCK(3) P3_KBLOCK(4)
        P3_KBLOCK(5) P3_KBLOCK(6) P3_KBLOCK(7)
        #undef P3_KBLOCK
        #undef P3_ACCK

        __syncthreads();   // (A) everyone done reading xs

        // store new state (conflict-free-throughput vectorized)
        #pragma unroll
        for (int m = 0; m < 8; m++) {
            float* xr = &xs[(riq + 8 * m) * BATCH + bq];
            *(ulonglong2*)xr       = make_ulonglong2(acc[m][0], acc[m][1]);
            *(ulonglong2*)(xr + 4) = make_ulonglong2(acc[m][2], acc[m][3]);
        }
        // stage next A,B into the other buffer (protected by barrier B)
        if (t < TCH - 1) {
            p3_stage_A(As + (cur ^ 1) * (NORD * P3_APAD), apf, tid);
            if (tid < 16) ((float4*)(Bs + (cur ^ 1) * NORD))[tid] = bpf;
        }
        __syncthreads();   // (B) state + staged A visible

        // copy out x_t: thread = batch column tid, coalesced STG.128
        {
            float* op = out + ((size_t)(t0 + t) * BATCH + tid) * NORD;
            const float* col = xs + tid;
            #pragma unroll
            for (int i4 = 0; i4 < 16; i4++) {
                float4 v = make_float4(col[(4 * i4 + 0) * BATCH],
                                       col[(4 * i4 + 1) * BATCH],
                                       col[(4 * i4 + 2) * BATCH],
                                       col[(4 * i4 + 3) * BATCH]);
                *(float4*)(op + 4 * i4) = v;
            }
        }
        cur ^= 1;
    }
}

// ---------------------------------------------------------------------------
extern "C" void kernel_launch(void* const* d_in, const int* in_sizes, int n_in,
                              void* d_out, int out_size)
{
    const float* inp = (const float*)d_in[0];   // (L, BATCH)
    const float* A   = (const float*)d_in[1];   // (L, N, N)
    const float* Bv  = (const float*)d_in[2];   // (L, N)
    float* out = (float*)d_out;                 // (L, BATCH, N)

    cudaFuncSetAttribute(phase3_kernel, cudaFuncAttributeMaxDynamicSharedMemorySize, P3_SMEM);

    phase1_kernel<<<CCH, 256>>>(A, Bv, inp);
    phase2_kernel<<<BATCH / 4, 256>>>();
    phase3_kernel<<<CCH, 256, P3_SMEM>>>(A, Bv, inp, out);
}

// round 9
// speedup vs baseline: 1.1967x; 1.0916x over previous
#include <cuda_runtime.h>
#include <cstdint>

#define L_SEQ 4096
#define BATCH 256
#define NORD  64
#define TCH   32
#define CCH   128   // L_SEQ / TCH
#define BS3   128   // batch half per phase-3 CTA

typedef unsigned long long ull;

__device__ __forceinline__ ull bcast2(float a) {
    ull r; asm("mov.b64 %0, {%1, %1};" : "=l"(r) : "f"(a)); return r;
}
__device__ __forceinline__ void ffma2(ull &d, ull a, ull b) {
    asm("fma.rn.f32x2 %0, %1, %2, %0;" : "+l"(d) : "l"(a), "l"(b));
}
__device__ __forceinline__ float2 unpack2(ull v) {
    float2 f; asm("mov.b64 {%0, %1}, %2;" : "=f"(f.x), "=f"(f.y) : "l"(v)); return f;
}

// Scratch (static device globals: no allocations allowed)
__device__ float g_P[(size_t)CCH * NORD * NORD];   // [c][i][j]  row-major P_c   2 MB
__device__ float g_S[(size_t)CCH * BATCH * NORD];  // [c][b][i]  chunk sources   8 MB
__device__ float g_X[(size_t)CCH * BATCH * NORD];  // [c][b][i]  boundary states 8 MB

// ---------------------------------------------------------------------------
// Phase 1 (unchanged, measured ~96us)
// ---------------------------------------------------------------------------
__global__ __launch_bounds__(256) void phase1_kernel(
    const float* __restrict__ A, const float* __restrict__ Bv,
    const float* __restrict__ inp)
{
    __shared__ float Pt[NORD * NORD];
    __shared__ float As[NORD * NORD];
    __shared__ float Bs[NORD];
    __shared__ float W[TCH][NORD];

    const int c = blockIdx.x, tid = threadIdx.x;
    const int t0 = c * TCH;
    const int ri = (tid & 15) * 4;   // i-tile
    const int cj = (tid >> 4) * 4;   // j-tile

    for (int idx = tid; idx < NORD * NORD; idx += 256)
        Pt[idx] = ((idx >> 6) == (idx & 63)) ? 1.f : 0.f;
    {
        const float4* A4 = (const float4*)(A + (size_t)(t0 + TCH - 1) * (NORD * NORD));
        float4* As4 = (float4*)As;
        #pragma unroll
        for (int q = 0; q < 4; q++) As4[tid + q * 256] = A4[tid + q * 256];
        if (tid < 16)
            ((float4*)Bs)[tid] = ((const float4*)(Bv + (size_t)(t0 + TCH - 1) * NORD))[tid];
    }
    __syncthreads();

    #pragma unroll 1
    for (int t = TCH - 1; t >= 0; --t) {
        float4 apf0, apf1, apf2, apf3, bpf;
        if (t > 0) {
            const float4* An = (const float4*)(A + (size_t)(t0 + t - 1) * (NORD * NORD));
            apf0 = An[tid]; apf1 = An[tid + 256]; apf2 = An[tid + 512]; apf3 = An[tid + 768];
            if (tid < 16) bpf = ((const float4*)(Bv + (size_t)(t0 + t - 1) * NORD))[tid];
        }

        float w0 = 0.f, w1 = 0.f, w2 = 0.f, w3 = 0.f;
        if (tid < NORD) {
            #pragma unroll
            for (int k4 = 0; k4 < 16; k4++) {
                w0 += Pt[(4 * k4 + 0) * NORD + tid] * Bs[4 * k4 + 0];
                w1 += Pt[(4 * k4 + 1) * NORD + tid] * Bs[4 * k4 + 1];
                w2 += Pt[(4 * k4 + 2) * NORD + tid] * Bs[4 * k4 + 2];
                w3 += Pt[(4 * k4 + 3) * NORD + tid] * Bs[4 * k4 + 3];
            }
        }

        ull acc2[4][2];
        #pragma unroll
        for (int jj = 0; jj < 4; jj++) { acc2[jj][0] = 0ull; acc2[jj][1] = 0ull; }

        #pragma unroll 8
        for (int k = 0; k < NORD; k++) {
            ulonglong2 p = *(const ulonglong2*)&Pt[k * NORD + ri];
            float4 a = *(const float4*)&As[k * NORD + cj];
            ull b0 = bcast2(a.x), b1 = bcast2(a.y), b2 = bcast2(a.z), b3 = bcast2(a.w);
            ffma2(acc2[0][0], b0, p.x); ffma2(acc2[0][1], b0, p.y);
            ffma2(acc2[1][0], b1, p.x); ffma2(acc2[1][1], b1, p.y);
            ffma2(acc2[2][0], b2, p.x); ffma2(acc2[2][1], b2, p.y);
            ffma2(acc2[3][0], b3, p.x); ffma2(acc2[3][1], b3, p.y);
        }
        __syncthreads();

        if (tid < NORD) W[t][tid] = (w0 + w1) + (w2 + w3);
        if (t > 0) {
            #pragma unroll
            for (int jj = 0; jj < 4; jj++)
                *(ulonglong2*)&Pt[(cj + jj) * NORD + ri] =
                    make_ulonglong2(acc2[jj][0], acc2[jj][1]);
            float4* As4 = (float4*)As;
            As4[tid] = apf0; As4[tid + 256] = apf1; As4[tid + 512] = apf2; As4[tid + 768] = apf3;
            if (tid < 16) ((float4*)Bs)[tid] = bpf;
        } else {
            float f[4][4];
            #pragma unroll
            for (int jj = 0; jj < 4; jj++) {
                float2 v0 = unpack2(acc2[jj][0]); f[jj][0] = v0.x; f[jj][1] = v0.y;
                float2 v1 = unpack2(acc2[jj][1]); f[jj][2] = v1.x; f[jj][3] = v1.y;
            }
            float* gp = g_P + (size_t)c * (NORD * NORD);
            #pragma unroll
            for (int ii = 0; ii < 4; ii++)
                *(float4*)&gp[(ri + ii) * NORD + cj] =
                    make_float4(f[0][ii], f[1][ii], f[2][ii], f[3][ii]);
        }
        __syncthreads();
    }

    {
        float u[TCH];
        #pragma unroll
        for (int tt = 0; tt < TCH; tt++) u[tt] = inp[(size_t)(t0 + tt) * BATCH + tid];
        float* sp = g_S + ((size_t)c * BATCH + tid) * NORD;
        #pragma unroll
        for (int half = 0; half < 2; half++) {
            ull acc[16];
            #pragma unroll
            for (int m = 0; m < 16; m++) acc[m] = 0ull;
            #pragma unroll 4
            for (int tt = 0; tt < TCH; tt++) {
                ull ub = bcast2(u[tt]);
                const ull* wrow = (const ull*)&W[tt][half * 32];
                #pragma unroll
                for (int m = 0; m < 16; m++) ffma2(acc[m], ub, wrow[m]);
            }
            #pragma unroll
            for (int m2 = 0; m2 < 8; m2++)
                *(ulonglong2*)&sp[half * 32 + m2 * 4] =
                    make_ulonglong2(acc[2 * m2], acc[2 * m2 + 1]);
        }
    }
}

// ---------------------------------------------------------------------------
// Phase 2 (unchanged): X_c = P_c @ X_{c-1} + S_c
// ---------------------------------------------------------------------------
#define P2PAD 68
__global__ __launch_bounds__(256) void phase2_kernel()
{
    __shared__ float Ps[2][NORD * P2PAD];
    __shared__ float xsm[2][4][NORD];

    const int tid = threadIdx.x;
    const int b0 = blockIdx.x * 4;
    const int i  = tid >> 2;
    const int bb = tid & 3;

    {
        const float4* gp = (const float4*)g_P;
        #pragma unroll
        for (int q = 0; q < 4; q++) {
            int f = tid + q * 256;
            int ii = f >> 4, j4 = f & 15;
            *(float4*)&Ps[0][ii * P2PAD + j4 * 4] = gp[f];
        }
        xsm[0][bb][i] = 0.f;
    }
    float s_cur = g_S[((size_t)b0 + bb) * NORD + i];
    __syncthreads();

    int cur = 0;
    #pragma unroll 1
    for (int c = 0; c < CCH; c++) {
        float4 pf0, pf1, pf2, pf3; float s_nxt = 0.f;
        if (c + 1 < CCH) {
            const float4* gp = (const float4*)(g_P + (size_t)(c + 1) * (NORD * NORD));
            pf0 = gp[tid]; pf1 = gp[tid + 256]; pf2 = gp[tid + 512]; pf3 = gp[tid + 768];
            s_nxt = g_S[((size_t)(c + 1) * BATCH + b0 + bb) * NORD + i];
        }

        ull a0 = 0ull, a1 = 0ull, a2 = 0ull, a3 = 0ull;
        const float* prow = &Ps[cur][i * P2PAD];
        const float* xrow = &xsm[cur][bb][0];
        #pragma unroll
        for (int j8 = 0; j8 < 8; j8++) {
            ulonglong2 p0 = *(const ulonglong2*)(prow + j8 * 8);
            ulonglong2 p1 = *(const ulonglong2*)(prow + j8 * 8 + 4);
            ulonglong2 x0 = *(const ulonglong2*)(xrow + j8 * 8);
            ulonglong2 x1 = *(const ulonglong2*)(xrow + j8 * 8 + 4);
            ffma2(a0, p0.x, x0.x); ffma2(a1, p0.y, x0.y);
            ffma2(a2, p1.x, x1.x); ffma2(a3, p1.y, x1.y);
        }
        float2 f0 = unpack2(a0), f1 = unpack2(a1), f2 = unpack2(a2), f3 = unpack2(a3);
        float acc = s_cur + ((f0.x + f0.y) + (f1.x + f1.y)) + ((f2.x + f2.y) + (f3.x + f3.y));

        const int nxt = cur ^ 1;
        xsm[nxt][bb][i] = acc;
        g_X[((size_t)c * BATCH + b0 + bb) * NORD + i] = acc;
        if (c + 1 < CCH) {
            #pragma unroll
            for (int q = 0; q < 4; q++) {
                float4 pv = (q == 0) ? pf0 : (q == 1) ? pf1 : (q == 2) ? pf2 : pf3;
                int f = tid + q * 256;
                int ii = f >> 4, j4 = f & 15;
                *(float4*)&Ps[nxt][ii * P2PAD + j4 * 4] = pv;
            }
        }
        s_cur = s_nxt;
        __syncthreads();
        cur = nxt;
    }
}

// ---------------------------------------------------------------------------
// Phase 3 (NEW): 2 CTAs per chunk (batch halves of 128), 256 threads,
// __launch_bounds__(256,2) -> 2 CTAs/SM = 16 warps/SM (latency hiding).
// Thread (riq = tid>>5 warp-uniform, bq = 4*(tid&31)) owns rows {riq+8m}
// (interleaved for balance) x 4 batches.  A_t staged PERMUTED:
//   As[k][ (i&7)*8 + (i>>3) ] = A[i][k]
// so a warp's 8 rows are CONTIGUOUS -> 2 uniform-broadcast LDS.128 per k.
// Lower-triangular A: row riq+8m needs k <= riq+8m (warp-uniform k-blocks).
// ---------------------------------------------------------------------------
#define P3_APAD 68
#define P3_SMEM ((2 * NORD * P3_APAD + NORD * BS3 + 2 * NORD) * 4)

__device__ __forceinline__ void p3_stage_AB(float* As, float* Bs,
                                            const float4* apf, float4 bpf, int tid) {
    #pragma unroll
    for (int q = 0; q < 4; q++) {
        int f = tid + q * 256;              // float4 idx: i = f>>4, j = 4*(f&15)
        int i = f >> 4, j = (f & 15) * 4;
        int p = ((i & 7) << 3) | (i >> 3);  // permuted row position
        float4 v = apf[q];
        As[(j + 0) * P3_APAD + p] = v.x;
        As[(j + 1) * P3_APAD + p] = v.y;
        As[(j + 2) * P3_APAD + p] = v.z;
        As[(j + 3) * P3_APAD + p] = v.w;
    }
    if (tid < 16) {
        #pragma unroll
        for (int r = 0; r < 4; r++) {
            int i = 4 * tid + r;
            float v = (r == 0) ? bpf.x : (r == 1) ? bpf.y : (r == 2) ? bpf.z : bpf.w;
            Bs[((i & 7) << 3) | (i >> 3)] = v;
        }
    }
}

__global__ __launch_bounds__(256, 2) void phase3_kernel(
    const float* __restrict__ A, const float* __restrict__ Bv,
    const float* __restrict__ inp, float* __restrict__ out)
{
    extern __shared__ float sm[];
    float* As = sm;                           // [2][64][68] permuted A
    float* xs = sm + 2 * NORD * P3_APAD;      // [64][128]   xs[j][b]
    float* Bs = xs + NORD * BS3;              // [2][64]     permuted B

    const int tid = threadIdx.x;
    const int c   = blockIdx.x >> 1;
    const int b0  = (blockIdx.x & 1) * BS3;
    const int t0  = c * TCH;
    const int riq = tid >> 5;                 // warp-uniform row offset 0..7
    const int bq  = (tid & 31) * 4;           // 4 batches per thread

    // stage A,B for t=0; load u for t=0
    {
        const float4* A4 = (const float4*)(A + (size_t)t0 * (NORD * NORD));
        float4 apf[4];
        #pragma unroll
        for (int q = 0; q < 4; q++) apf[q] = A4[tid + q * 256];
        float4 bpf = make_float4(0.f, 0.f, 0.f, 0.f);
        if (tid < 16) bpf = ((const float4*)(Bv + (size_t)t0 * NORD))[tid];
        p3_stage_AB(As, Bs, apf, bpf, tid);
    }
    ulonglong2 ucur = *(const ulonglong2*)(inp + (size_t)t0 * BATCH + b0 + bq);

    // load initial state into xs[j][b]: thread = (bcol = tid&127, jhalf = tid>>7)
    {
        const int bcol = tid & 127, jhalf = tid >> 7;
        if (c == 0) {
            #pragma unroll
            for (int j = 0; j < 32; j++) xs[(jhalf * 32 + j) * BS3 + bcol] = 0.f;
        } else {
            const float4* Xp = (const float4*)(g_X + (((size_t)(c - 1)) * BATCH + b0 + bcol) * NORD + jhalf * 32);
            #pragma unroll
            for (int j4 = 0; j4 < 8; j4++) {
                float4 v = Xp[j4];
                xs[(jhalf * 32 + 4 * j4 + 0) * BS3 + bcol] = v.x;
                xs[(jhalf * 32 + 4 * j4 + 1) * BS3 + bcol] = v.y;
                xs[(jhalf * 32 + 4 * j4 + 2) * BS3 + bcol] = v.z;
                xs[(jhalf * 32 + 4 * j4 + 3) * BS3 + bcol] = v.w;
            }
        }
    }
    __syncthreads();

    int cur = 0;
    #pragma unroll 1
    for (int t = 0; t < TCH; t++) {
        // prefetch next A,B,u into registers
        float4 apf[4]; float4 bpf; ulonglong2 unxt;
        if (t < TCH - 1) {
            const float4* An = (const float4*)(A + (size_t)(t0 + t + 1) * (NORD * NORD));
            #pragma unroll
            for (int q = 0; q < 4; q++) apf[q] = An[tid + q * 256];
            if (tid < 16) bpf = ((const float4*)(Bv + (size_t)(t0 + t + 1) * NORD))[tid];
            unxt = *(const ulonglong2*)(inp + (size_t)(t0 + t + 1) * BATCH + b0 + bq);
        }

        const float* Ac = As + cur * (NORD * P3_APAD);
        const float* Bc = Bs + cur * NORD;

        // init acc[m] = B[row]*u
        ull acc[8][2];
        {
            float4 B0 = *(const float4*)&Bc[riq * 8];
            float4 B1 = *(const float4*)&Bc[riq * 8 + 4];
            float bb[8] = {B0.x, B0.y, B0.z, B0.w, B1.x, B1.y, B1.z, B1.w};
            #pragma unroll
            for (int m = 0; m < 8; m++) {
                ull ab = bcast2(bb[m]);
                acc[m][0] = 0ull; acc[m][1] = 0ull;
                ffma2(acc[m][0], ab, ucur.x); ffma2(acc[m][1], ab, ucur.y);
            }
        }

        // triangular MACs: row riq+8m active for k <= riq+8m
        #define P3_ACCK(K, MSTART)                                              \
        {                                                                       \
            ulonglong2 X = *(const ulonglong2*)&xs[(K) * BS3 + bq];             \
            float a[8];                                                         \
            if ((MSTART) < 4) {                                                 \
                float4 A0 = *(const float4*)&Ac[(K) * P3_APAD + riq * 8];       \
                a[0] = A0.x; a[1] = A0.y; a[2] = A0.z; a[3] = A0.w;             \
            }                                                                   \
            {                                                                   \
                float4 A1 = *(const float4*)&Ac[(K) * P3_APAD + riq * 8 + 4];   \
                a[4] = A1.x; a[5] = A1.y; a[6] = A1.z; a[7] = A1.w;             \
            }                                                                   \
            _Pragma("unroll")                                                   \
            for (int m = (MSTART); m < 8; m++) {                                \
                ull ab = bcast2(a[m]);                                          \
                ffma2(acc[m][0], ab, X.x); ffma2(acc[m][1], ab, X.y);           \
            }                                                                   \
        }

        // block 0: k = 0..riq (warp-uniform trip), all rows
        #pragma unroll 1
        for (int k = 0; k <= riq; k++) P3_ACCK(k, 0);

        // KBLOCK(MB): 8 k's in [riq+8(MB-1)+1, riq+8MB], rows m >= MB
        #define P3_KBLOCK(MB)                                                   \
        {                                                                       \
            const int kbase = riq + 8 * ((MB) - 1) + 1;                         \
            _Pragma("unroll")                                                   \
            for (int kk = 0; kk < 8; kk++) P3_ACCK(kbase + kk, MB);             \
        }
        P3_KBLOCK(1) P3_KBLOCK(2) P3_KBLOCK(3) P3_KBLOCK(4)
        P3_KBLOCK(5) P3_KBLOCK(6) P3_KBLOCK(7)
        #undef P3_KBLOCK
        #undef P3_ACCK

        __syncthreads();   // (A) everyone done reading xs

        // store new state (16B lane stride -> conflict-free)
        #pragma unroll
        for (int m = 0; m < 8; m++)
            *(ulonglong2*)&xs[(riq + 8 * m) * BS3 + bq] =
                make_ulonglong2(acc[m][0], acc[m][1]);
        // stage next A,B into the other buffer
        if (t < TCH - 1)
            p3_stage_AB(As + (cur ^ 1) * (NORD * P3_APAD), Bs + (cur ^ 1) * NORD,
                        apf, bpf, tid);
        __syncthreads();   // (B) state + staged A visible

        // copy out x_t: thread = (bcol, ihalf); 8 contiguous STG.128 per thread
        {
            const int bcol = tid & 127, ihalf = tid >> 7;
            float* op = out + ((size_t)(t0 + t) * BATCH + b0 + bcol) * NORD + ihalf * 32;
            const float* col = xs + bcol;
            #pragma unroll
            for (int i4 = 0; i4 < 8; i4++) {
                float4 v = make_float4(col[(ihalf * 32 + 4 * i4 + 0) * BS3],
                                       col[(ihalf * 32 + 4 * i4 + 1) * BS3],
                                       col[(ihalf * 32 + 4 * i4 + 2) * BS3],
                                       col[(ihalf * 32 + 4 * i4 + 3) * BS3]);
                *(float4*)(op + 4 * i4) = v;
            }
        }
        ucur = unxt;
        cur ^= 1;
    }
}

// ---------------------------------------------------------------------------
extern "C" void kernel_launch(void* const* d_in, const int* in_sizes, int n_in,
                              void* d_out, int out_size)
{
    const float* inp = (const float*)d_in[0];   // (L, BATCH)
    const float* A   = (const float*)d_in[1];   // (L, N, N)
    const float* Bv  = (const float*)d_in[2];   // (L, N)
    float* out = (float*)d_out;                 // (L, BATCH, N)

    cudaFuncSetAttribute(phase3_kernel, cudaFuncAttributeMaxDynamicSharedMemorySize, P3_SMEM);

    phase1_kernel<<<CCH, 256>>>(A, Bv, inp);
    phase2_kernel<<<BATCH / 4, 256>>>();
    phase3_kernel<<<CCH * 2, 256, P3_SMEM>>>(A, Bv, inp, out);
}